// round 8
// baseline (speedup 1.0000x reference)
#include <cuda_runtime.h>

// Problem constants (fixed by setup_inputs)
#define B     128
#define NPIX  2048
#define NBINS 1500
#define NBF   250
#define NREP  256
#define TSIM  1250   // len_bins_sim
#define NBLK  40     // ceil(TSIM/32)
#define N1    ((size_t)B * NREP * NBINS)   // start of gensig region in d_out

#define NLOG2E (-1.4426950408889634f)
#define LN2    (0.6931471805599453f)

// Global staging: one 128B line per (b, segment)
__device__ __align__(128) float g_spk[B * 1280];
__device__ __align__(128) float g_gsg[B * 1280];
__device__ int g_prog[B];

__device__ __forceinline__ float fex2(float x) {
    float r; asm("ex2.approx.ftz.f32 %0, %1;" : "=f"(r) : "f"(x)); return r;
}
__device__ __forceinline__ float frcp(float x) {
    float r; asm("rcp.approx.ftz.f32 %0, %1;" : "=f"(r) : "f"(x)); return r;
}

__global__ void k_reset() { if (threadIdx.x < B) g_prog[threadIdx.x] = 0; }

// ---------------------------------------------------------------------------
// ONE main kernel, two CTA roles:
//  blocks 0..127   (producers, one per batch b):
//    setup  : filters, spatial dot, 1250-pt correlation, drive sh_g
//    warp 7 : serial z-space chain, 32 steps per iteration
//    warp 6 : publishes finished segments to global staging + flags,
//             then pipelined precompute of next block's history partials
//    warps 0-5: in-CTA broadcast of repeats 0..63 (paced by sh_prog)
//  blocks 128..383 (writers, two per batch, 96 repeats each):
//    poll g_prog[b], read staging via __ldcg, stream segments with __stcs
// ---------------------------------------------------------------------------
__global__ __launch_bounds__(256, 3) void k_all(
    const float* __restrict__ A,    // (128, 2048)
    const float* __restrict__ st,   // (1500,)
    const float* __restrict__ init, // (128, 250)
    const float* __restrict__ sf,   // (2048,)
    const float* __restrict__ tf,   // (250,)
    const float* __restrict__ fbf,  // (250,)
    const float* __restrict__ bias, // (1,)
    float* __restrict__ out)
{
    int tid = threadIdx.x;
    int warp = tid >> 5, lane = tid & 31;
    float* outG = out + N1;

    if (blockIdx.x >= B) {
        // ======================= WRITER CTA =======================
        int w = blockIdx.x - B;            // 0..255
        int b = w >> 1;
        int r0 = 64 + (w & 1) * 96;        // repeats [r0, r0+96)
        size_t rowT = (size_t)(b * NREP + r0 + warp) * NBINS;
        size_t rowG = (size_t)(b * NREP + r0 + warp) * TSIM;

        // init section: 250 floats = 125 float2 per repeat (no dependency)
        {
            const float2* ini2 = (const float2*)(init + b * NBF);
            float2 v0 = __ldg(ini2 + lane);
            float2 v1 = __ldg(ini2 + lane + 32);
            float2 v2 = __ldg(ini2 + lane + 64);
            bool has3 = (lane + 96) < 125;
            float2 v3 = has3 ? __ldg(ini2 + lane + 96) : make_float2(0.f, 0.f);
            float* base = out + rowT;
            #pragma unroll 4
            for (int i = 0; i < 12; i++) {       // repeats r0+warp, step 8 (12 each)
                float2* d = (float2*)base;
                __stcs(d + lane, v0);
                __stcs(d + lane + 32, v1);
                __stcs(d + lane + 64, v2);
                if (has3) __stcs(d + lane + 96, v3);
                base += (size_t)8 * NBINS;
            }
        }

        bool isT = lane < 16;
        int sub = isT ? lane : lane - 16;
        const float* stg = isT ? g_spk : g_gsg;
        size_t stride = isT ? (size_t)8 * NBINS : (size_t)8 * TSIM;
        volatile int* pf = g_prog + b;

        for (int seg = 0; seg < NBLK; seg++) {
            while (*pf < seg + 1) __nanosleep(64);
            __threadfence();
            int width = (seg < NBLK - 1) ? 32 : 2;       // last seg: t=1248,1249
            if (2 * sub < width) {
                float2 v = __ldcg((const float2*)(stg + b * 1280 + seg * 32 + 2 * sub));
                float* p = isT ? out + rowT + 250 + seg * 32 + 2 * sub
                               : outG + rowG + seg * 32 + 2 * sub;
                #pragma unroll 4
                for (int i = 0; i < 12; i++) {
                    __stcs((float2*)p, v);
                    p += stride;
                }
            }
        }
        return;
    }

    // ======================= PRODUCER CTA =======================
    __shared__ __align__(16) float sh_tl[1504];   // timeline (init + spikes)
    __shared__ __align__(16) float sh_f[288];     // feedback filter, zero-padded
    __shared__ __align__(16) float sh_fw[288];    // -log2e * filter
    __shared__ __align__(16) float sh_g[1280];    // drive; overwritten w/ gensig
    __shared__ __align__(16) float sh_tc[256];    // timecourse filter
    __shared__ __align__(16) float sh_st[1504];   // stim_time
    __shared__ float red[256];
    __shared__ float sh_pre[2][32];
    __shared__ int   sh_prog;

    int b = blockIdx.x;

    // ------------------------- setup -------------------------
    if (tid == 0) sh_prog = 0;
    if (tid < NBF) {
        sh_f[tid]  = fbf[tid];
        sh_tc[tid] = tf[tid];
        sh_tl[tid] = init[b * NBF + tid];
    } else if (tid < 288) sh_f[tid] = 0.f;
    for (int j = tid; j < NBINS; j += 256) sh_st[j] = st[j];
    {   // spatial dot partials (2 float4 per thread)
        const float4* row4 = (const float4*)(A + (size_t)b * NPIX);
        const float4* sf4  = (const float4*)sf;
        float4 a0 = row4[tid], f0 = sf4[tid];
        float4 a1 = row4[tid + 256], f1 = sf4[tid + 256];
        red[tid] = a0.x*f0.x + a0.y*f0.y + a0.z*f0.z + a0.w*f0.w
                 + a1.x*f1.x + a1.y*f1.y + a1.z*f1.z + a1.w*f1.w;
    }
    __syncthreads();

    if (tid < 288) sh_fw[tid] = NLOG2E * sh_f[tid];
    if (warp == 0) {   // reduce spatial dot
        float r = 0.f;
        #pragma unroll
        for (int k = 0; k < 8; k++) r += red[lane + 32 * k];
        #pragma unroll
        for (int o = 16; o > 0; o >>= 1) r += __shfl_xor_sync(0xffffffffu, r, o);
        if (lane == 0) red[0] = r;
    }
    // correlation: 5 t-values per thread (covers 0..1279)
    float corr[5];
    #pragma unroll
    for (int u = 0; u < 5; u++) {
        int t = tid + 256 * u;
        float a0 = 0, a1 = 0, a2 = 0, a3 = 0;
        if (t < TSIM) {
            for (int j = 0; j < 248; j += 4) {
                a0 = fmaf(sh_st[t + j],     sh_tc[j],     a0);
                a1 = fmaf(sh_st[t + j + 1], sh_tc[j + 1], a1);
                a2 = fmaf(sh_st[t + j + 2], sh_tc[j + 2], a2);
                a3 = fmaf(sh_st[t + j + 3], sh_tc[j + 3], a3);
            }
            a0 = fmaf(sh_st[t + 248], sh_tc[248], a0);
            a1 = fmaf(sh_st[t + 249], sh_tc[249], a1);
        }
        corr[u] = (a0 + a1) + (a2 + a3);
    }
    __syncthreads();
    {
        float fs = red[0], bv = bias[0];
        #pragma unroll
        for (int u = 0; u < 5; u++) {
            int t = tid + 256 * u;
            sh_g[t] = (t < TSIM) ? fmaf(fs, corr[u], bv) : 0.f;
        }
    }
    __syncthreads();

    // ------------------------- role split -------------------------
    if (warp == 7) {
        // ---------------- serial chain (z-space) ----------------
        {   // block-0 precompute: all taps from initial history
            int lim = 250 - lane;
            float a0 = 0, a1 = 0, a2 = 0, a3 = 0;
            int j = 0;
            for (; j + 4 <= lim; j += 4) {
                a0 = fmaf(sh_tl[lane + j],     sh_f[j],     a0);
                a1 = fmaf(sh_tl[lane + j + 1], sh_f[j + 1], a1);
                a2 = fmaf(sh_tl[lane + j + 2], sh_f[j + 2], a2);
                a3 = fmaf(sh_tl[lane + j + 3], sh_f[j + 3], a3);
            }
            for (; j < lim; j++) a0 = fmaf(sh_tl[lane + j], sh_f[j], a0);
            sh_pre[0][lane] = (a0 + a1) + (a2 + a3);
        }
        int fchain = 250 - lane;   // chain tap base (sh_fw)
        int ffix   = 218 - lane;   // fixup tap base (sh_f)

        for (int m = 0; m < NBLK; m++) {
            asm volatile("bar.sync 1, 64;" ::: "memory");  // warps 6+7 only
            int T0 = m * 32, t = T0 + lane;
            float part = sh_pre[m & 1][lane] + sh_g[t];

            if (m > 0) {   // fixup: previous block's 32 spikes
                int base = 250 + T0 - 32;
                float a0 = 0, a1 = 0, a2 = 0, a3 = 0;
                #pragma unroll
                for (int k = 0; k < 32; k += 4) {
                    a0 = fmaf(sh_tl[base + k],     sh_f[ffix + k],     a0);
                    a1 = fmaf(sh_tl[base + k + 1], sh_f[ffix + k + 1], a1);
                    a2 = fmaf(sh_tl[base + k + 2], sh_f[ffix + k + 2], a2);
                    a3 = fmaf(sh_tl[base + k + 3], sh_f[ffix + k + 3], a3);
                }
                part += (a0 + a1) + (a2 + a3);
            }

            // z-space chain: sigmoid = rcp(1 + 2^z), z = -log2e * gensig.
            // sh_fw[fchain+k]==0 for k>=lane, so each lane's z freezes at its
            // own step; sl after the loop = sigmoid of the frozen gensig.
            float z = NLOG2E * part;
            float sl = 0.f;
            #pragma unroll
            for (int k = 0; k < 32; k++) {
                float e = fex2(z);
                sl = frcp(1.0f + e);
                float s = __shfl_sync(0xffffffffu, sl, k);
                z = fmaf(s, sh_fw[fchain + k], z);
            }

            int kmax = TSIM - T0; if (kmax > 32) kmax = 32;
            if (lane < kmax) {
                sh_tl[250 + t] = sl;          // spike_t
                sh_g[t] = -LN2 * z;           // gensig_t
            }
        }
        asm volatile("bar.sync 1, 64;" ::: "memory");      // epilogue match
    } else if (warp == 6) {
        // -------- publish previous segment, then precompute next --------
        for (int m = 0; m < NBLK; m++) {
            asm volatile("bar.sync 1, 64;" ::: "memory");
            if (m > 0) {   // publish segment m-1 (complete as of this barrier)
                int seg = m - 1;
                if (lane < 16) {
                    float2 v = *(const float2*)(sh_tl + 250 + seg * 32 + 2 * lane);
                    *(float2*)(g_spk + b * 1280 + seg * 32 + 2 * lane) = v;
                } else {
                    int sub = lane - 16;
                    float2 v = *(const float2*)(sh_g + seg * 32 + 2 * sub);
                    *(float2*)(g_gsg + b * 1280 + seg * 32 + 2 * sub) = v;
                }
                __syncwarp();
                if (lane == 0) {
                    __threadfence();
                    *(volatile int*)&g_prog[b] = seg + 1;
                    *(volatile int*)&sh_prog = seg + 1;
                }
            }
            if (m + 1 < NBLK) {   // precompute block m+1 (spikes through m-1)
                int T0n = m * 32 + 32;
                int lim = 218 - lane;
                float a0 = 0, a1 = 0, a2 = 0, a3 = 0;
                int j = 0;
                for (; j + 4 <= lim; j += 4) {
                    a0 = fmaf(sh_tl[T0n + lane + j],     sh_f[j],     a0);
                    a1 = fmaf(sh_tl[T0n + lane + j + 1], sh_f[j + 1], a1);
                    a2 = fmaf(sh_tl[T0n + lane + j + 2], sh_f[j + 2], a2);
                    a3 = fmaf(sh_tl[T0n + lane + j + 3], sh_f[j + 3], a3);
                }
                for (; j < lim; j++) a0 = fmaf(sh_tl[T0n + lane + j], sh_f[j], a0);
                sh_pre[(m + 1) & 1][lane] = (a0 + a1) + (a2 + a3);
            }
        }
        asm volatile("bar.sync 1, 64;" ::: "memory");
        {   // publish final segment 39 (only t = 1248, 1249)
            if (lane == 0) {
                *(float2*)(g_spk + b * 1280 + 39 * 32) = *(const float2*)(sh_tl + 1498);
                *(float2*)(g_gsg + b * 1280 + 39 * 32) = *(const float2*)(sh_g + 1248);
            }
            __syncwarp();
            if (lane == 0) {
                __threadfence();
                *(volatile int*)&g_prog[b] = NBLK;
                *(volatile int*)&sh_prog = NBLK;
            }
        }
    } else {
        // ---------------- in-CTA copy warps 0..5: repeats 0..63 ----------------
        int cw = warp;
        int reps = (64 - 1 - cw) / 6 + 1;            // 11 or 10
        size_t rowT0 = (size_t)(b * NREP + cw) * NBINS;
        size_t rowG0 = (size_t)(b * NREP + cw) * TSIM;
        volatile int* prog = &sh_prog;

        // init section
        {
            const float2* s2 = (const float2*)sh_tl;
            float2 v0 = s2[lane], v1 = s2[lane + 32], v2 = s2[lane + 64];
            bool has3 = (lane + 96) < 125;
            float2 v3 = has3 ? s2[lane + 96] : make_float2(0.f, 0.f);
            float* base = out + rowT0;
            for (int i = 0; i < reps; i++) {
                float2* d = (float2*)base;
                __stcs(d + lane, v0);
                __stcs(d + lane + 32, v1);
                __stcs(d + lane + 64, v2);
                if (has3) __stcs(d + lane + 96, v3);
                base += (size_t)6 * NBINS;
            }
        }

        bool isT = lane < 16;
        int sub = isT ? lane : lane - 16;
        size_t stride = isT ? (size_t)6 * NBINS : (size_t)6 * TSIM;

        for (int seg = 0; seg < NBLK; seg++) {
            while (*prog <= seg) __nanosleep(64);
            __threadfence_block();
            int tb = 250 + seg * 32, gb = seg * 32;
            int width = (seg < NBLK - 1) ? 32 : 2;
            if (2 * sub < width) {
                float2 v = isT ? *(const float2*)(sh_tl + tb + 2 * sub)
                               : *(const float2*)(sh_g + gb + 2 * sub);
                float* p = isT ? out + rowT0 + tb + 2 * sub
                               : outG + rowG0 + gb + 2 * sub;
                #pragma unroll 4
                for (int i = 0; i < reps; i++) {
                    __stcs((float2*)p, v);
                    p += stride;
                }
            }
        }
    }
}

// ---------------------------------------------------------------------------
extern "C" void kernel_launch(void* const* d_in, const int* in_sizes, int n_in,
                              void* d_out, int out_size) {
    const float* A    = (const float*)d_in[0];  // (128, 2048)
    const float* st   = (const float*)d_in[1];  // (1500,)
    const float* init = (const float*)d_in[2];  // (128, 250)
    int off = (n_in >= 8) ? 1 : 0;              // skip n_repeats scalar if present
    const float* sf = (const float*)d_in[3 + off];  // (2048,)
    const float* tf = (const float*)d_in[4 + off];  // (250,)
    const float* fb = (const float*)d_in[5 + off];  // (250,)
    const float* bi = (const float*)d_in[6 + off];  // (1,)

    k_reset<<<1, 128>>>();
    k_all<<<B + 2 * B, 256>>>(A, st, init, sf, tf, fb, bi, (float*)d_out);
}

// round 10
// speedup vs baseline: 1.4659x; 1.4659x over previous
#include <cuda_runtime.h>

// Problem constants (fixed by setup_inputs)
#define B     128
#define NPIX  2048
#define NBINS 1500
#define NBF   250
#define NREP  256
#define TSIM  1250   // len_bins_sim
#define NBLK  40     // ceil(TSIM/32)
#define N1    ((size_t)B * NREP * NBINS)   // start of gensig region in d_out

#define NLOG2E (-1.4426950408889634f)
#define LN2    (0.6931471805599453f)
#define NCW    30    // copy warps per CTA

__device__ __forceinline__ float fex2(float x) {
    float r; asm("ex2.approx.ftz.f32 %0, %1;" : "=f"(r) : "f"(x)); return r;
}
__device__ __forceinline__ float frcp(float x) {
    float r; asm("rcp.approx.ftz.f32 %0, %1;" : "=f"(r) : "f"(x)); return r;
}

// ---------------------------------------------------------------------------
// ONE kernel, 128 CTAs x 1024 threads (one CTA per batch):
//   setup     : all warps — filters, spatial dot, 1250-pt correlation, drive
//   warp 31   : serial z-space chain (highest arbiter priority), 32 steps/iter,
//               publishes finished segments via shared progress flag
//   warp 30   : pipelined precompute of next block's history-only partials
//   warps 0-29: stream finished segments to all 256 repeats (30 store
//               warps/SM -> enough outstanding stores to approach the DRAM
//               write ceiling), paced by the shared flag; never block the chain
//
// Timeline coords: tl[k]=init[k] for k<250, tl[250+t]=spike_t.
// fb_t = sum_{j=0..249} tl[t+j] * f[j].
// For block at T0, lane i (t=T0+i):
//   - taps j in [0, 217-i]   : spikes through block m-2 -> warp-30 precompute
//   - taps j in [218-i,249-i]: block m-1 spikes         -> 32-tap fixup
//   - taps j in [250-i,249]  : in-block spikes          -> serial shfl chain
// ---------------------------------------------------------------------------
__global__ __launch_bounds__(1024, 1) void k_all(
    const float* __restrict__ A,    // (128, 2048)
    const float* __restrict__ st,   // (1500,)
    const float* __restrict__ init, // (128, 250)
    const float* __restrict__ sf,   // (2048,)
    const float* __restrict__ tf,   // (250,)
    const float* __restrict__ fbf,  // (250,)
    const float* __restrict__ bias, // (1,)
    float* __restrict__ out)
{
    __shared__ __align__(16) float sh_tl[1504];   // timeline (init + spikes)
    __shared__ __align__(16) float sh_f[288];     // feedback filter, zero-padded
    __shared__ __align__(16) float sh_fw[288];    // -log2e * filter
    __shared__ __align__(16) float sh_g[1280];    // drive; overwritten w/ gensig
    __shared__ __align__(16) float sh_tc[256];    // timecourse filter
    __shared__ __align__(16) float sh_st[1504];   // stim_time
    __shared__ float red[512];
    __shared__ float sh_pre[2][32];
    __shared__ int   sh_prog;                     // segments produced (0..NBLK)

    int b = blockIdx.x, tid = threadIdx.x;
    int warp = tid >> 5, lane = tid & 31;
    float* outG = out + N1;

    // ------------------------- setup -------------------------
    if (tid == 0) sh_prog = 0;
    if (tid < NBF) {
        sh_f[tid]  = fbf[tid];
        sh_tc[tid] = tf[tid];
        sh_tl[tid] = init[b * NBF + tid];
    } else if (tid < 288) sh_f[tid] = 0.f;
    if (tid < NBINS) sh_st[tid] = st[tid];
    else if (tid - 1024 >= 0 && tid - 1024 + 1024 < NBINS) {}  // (unused)
    if (tid + 1024 < NBINS) sh_st[tid + 1024] = st[tid + 1024];
    if (tid < 512) {   // spatial dot partials (one float4 per thread)
        const float4* row4 = (const float4*)(A + (size_t)b * NPIX);
        const float4* sf4  = (const float4*)sf;
        float4 a = row4[tid], f = sf4[tid];
        red[tid] = a.x*f.x + a.y*f.y + a.z*f.z + a.w*f.w;
    }
    __syncthreads();

    if (tid < 288) sh_fw[tid] = NLOG2E * sh_f[tid];
    if (warp == 0) {   // reduce spatial dot
        float r = 0.f;
        #pragma unroll
        for (int k = 0; k < 16; k++) r += red[lane + 32 * k];
        #pragma unroll
        for (int o = 16; o > 0; o >>= 1) r += __shfl_xor_sync(0xffffffffu, r, o);
        if (lane == 0) red[0] = r;
    }
    // correlation: 2 t-values per thread (t = tid, tid + 1024)
    float c0 = 0.f, c1 = 0.f;
    {
        int t0 = tid, t1 = tid + 1024;
        float a0 = 0, a1 = 0, a2 = 0, a3 = 0;
        for (int j = 0; j < 248; j += 4) {
            a0 = fmaf(sh_st[t0 + j],     sh_tc[j],     a0);
            a1 = fmaf(sh_st[t0 + j + 1], sh_tc[j + 1], a1);
            a2 = fmaf(sh_st[t0 + j + 2], sh_tc[j + 2], a2);
            a3 = fmaf(sh_st[t0 + j + 3], sh_tc[j + 3], a3);
        }
        a0 = fmaf(sh_st[t0 + 248], sh_tc[248], a0);
        a1 = fmaf(sh_st[t0 + 249], sh_tc[249], a1);
        c0 = (a0 + a1) + (a2 + a3);
        if (t1 < TSIM) {
            float b0 = 0, b1 = 0, b2 = 0, b3 = 0;
            for (int j = 0; j < 248; j += 4) {
                b0 = fmaf(sh_st[t1 + j],     sh_tc[j],     b0);
                b1 = fmaf(sh_st[t1 + j + 1], sh_tc[j + 1], b1);
                b2 = fmaf(sh_st[t1 + j + 2], sh_tc[j + 2], b2);
                b3 = fmaf(sh_st[t1 + j + 3], sh_tc[j + 3], b3);
            }
            b0 = fmaf(sh_st[t1 + 248], sh_tc[248], b0);
            b1 = fmaf(sh_st[t1 + 249], sh_tc[249], b1);
            c1 = (b0 + b1) + (b2 + b3);
        }
    }
    __syncthreads();
    {
        float fs = red[0], bv = bias[0];
        sh_g[tid] = (tid < TSIM) ? fmaf(fs, c0, bv) : 0.f;
        if (tid + 1024 < 1280)
            sh_g[tid + 1024] = (tid + 1024 < TSIM) ? fmaf(fs, c1, bv) : 0.f;
    }
    __syncthreads();

    // ------------------------- role split -------------------------
    if (warp == 31) {
        // ---------------- serial chain (z-space) ----------------
        {   // block-0 precompute: all taps from initial history
            int lim = 250 - lane;
            float a0 = 0, a1 = 0, a2 = 0, a3 = 0;
            int j = 0;
            for (; j + 4 <= lim; j += 4) {
                a0 = fmaf(sh_tl[lane + j],     sh_f[j],     a0);
                a1 = fmaf(sh_tl[lane + j + 1], sh_f[j + 1], a1);
                a2 = fmaf(sh_tl[lane + j + 2], sh_f[j + 2], a2);
                a3 = fmaf(sh_tl[lane + j + 3], sh_f[j + 3], a3);
            }
            for (; j < lim; j++) a0 = fmaf(sh_tl[lane + j], sh_f[j], a0);
            sh_pre[0][lane] = (a0 + a1) + (a2 + a3);
        }
        int fchain = 250 - lane;   // chain tap base (sh_fw)
        int ffix   = 218 - lane;   // fixup tap base (sh_f)

        for (int m = 0; m < NBLK; m++) {
            asm volatile("bar.sync 1, 64;" ::: "memory");  // warps 30+31 only
            int T0 = m * 32, t = T0 + lane;
            float part = sh_pre[m & 1][lane] + sh_g[t];

            if (m > 0) {   // fixup: previous block's 32 spikes
                int base = 250 + T0 - 32;
                float a0 = 0, a1 = 0, a2 = 0, a3 = 0;
                #pragma unroll
                for (int k = 0; k < 32; k += 4) {
                    a0 = fmaf(sh_tl[base + k],     sh_f[ffix + k],     a0);
                    a1 = fmaf(sh_tl[base + k + 1], sh_f[ffix + k + 1], a1);
                    a2 = fmaf(sh_tl[base + k + 2], sh_f[ffix + k + 2], a2);
                    a3 = fmaf(sh_tl[base + k + 3], sh_f[ffix + k + 3], a3);
                }
                part += (a0 + a1) + (a2 + a3);
            }

            // z-space chain: sigmoid = rcp(1 + 2^z), z = -log2e * gensig.
            // sh_fw[fchain+k]==0 for k>=lane, so each lane's z freezes at its
            // own step; sl after the loop = sigmoid of the frozen gensig.
            float z = NLOG2E * part;
            float sl = 0.f;
            #pragma unroll
            for (int k = 0; k < 32; k++) {
                float e = fex2(z);
                sl = frcp(1.0f + e);
                float s = __shfl_sync(0xffffffffu, sl, k);
                z = fmaf(s, sh_fw[fchain + k], z);
            }

            int kmax = TSIM - T0; if (kmax > 32) kmax = 32;
            if (lane < kmax) {
                sh_tl[250 + t] = sl;          // spike_t
                sh_g[t] = -LN2 * z;           // gensig_t
            }
            __syncwarp();                     // memory-ordered within warp
            if (lane == 0) { __threadfence_block(); *(volatile int*)&sh_prog = m + 1; }
        }
    } else if (warp == 30) {
        // ---------------- pipelined precompute ----------------
        for (int m = 0; m < NBLK; m++) {
            asm volatile("bar.sync 1, 64;" ::: "memory");
            if (m + 1 < NBLK) {   // block m+1 partials over spikes through m-1
                int T0n = m * 32 + 32;
                int lim = 218 - lane;
                float a0 = 0, a1 = 0, a2 = 0, a3 = 0;
                int j = 0;
                for (; j + 4 <= lim; j += 4) {
                    a0 = fmaf(sh_tl[T0n + lane + j],     sh_f[j],     a0);
                    a1 = fmaf(sh_tl[T0n + lane + j + 1], sh_f[j + 1], a1);
                    a2 = fmaf(sh_tl[T0n + lane + j + 2], sh_f[j + 2], a2);
                    a3 = fmaf(sh_tl[T0n + lane + j + 3], sh_f[j + 3], a3);
                }
                for (; j < lim; j++) a0 = fmaf(sh_tl[T0n + lane + j], sh_f[j], a0);
                sh_pre[(m + 1) & 1][lane] = (a0 + a1) + (a2 + a3);
            }
        }
    } else {
        // ---------------- copy warps 0..29: all 256 repeats ----------------
        int cw = warp;                                // 0..29
        int reps = (NREP - 1 - cw) / NCW + 1;         // 9 or 8
        size_t rowT0 = (size_t)(b * NREP + cw) * NBINS;
        size_t rowG0 = (size_t)(b * NREP + cw) * TSIM;
        volatile int* prog = &sh_prog;

        // init section: 250 floats = 125 float2 per repeat (no dependency)
        {
            const float2* s2 = (const float2*)sh_tl;
            float2 v0 = s2[lane], v1 = s2[lane + 32], v2 = s2[lane + 64];
            bool has3 = (lane + 96) < 125;
            float2 v3 = has3 ? s2[lane + 96] : make_float2(0.f, 0.f);
            float* base = out + rowT0;
            for (int i = 0; i < reps; i++) {
                float2* d = (float2*)base;
                __stcs(d + lane, v0);
                __stcs(d + lane + 32, v1);
                __stcs(d + lane + 64, v2);
                if (has3) __stcs(d + lane + 96, v3);
                base += (size_t)NCW * NBINS;
            }
        }

        bool isT = lane < 16;
        int sub = isT ? lane : lane - 16;
        size_t stride = isT ? (size_t)NCW * NBINS : (size_t)NCW * TSIM;

        for (int seg = 0; seg < NBLK; seg++) {
            while (*prog <= seg) __nanosleep(64);
            __threadfence_block();
            int tb = 250 + seg * 32, gb = seg * 32;
            int width = (seg < NBLK - 1) ? 32 : 2;    // last seg: t=1248,1249
            if (2 * sub < width) {
                float2 v = isT ? *(const float2*)(sh_tl + tb + 2 * sub)
                               : *(const float2*)(sh_g + gb + 2 * sub);
                float* p = isT ? out + rowT0 + tb + 2 * sub
                               : outG + rowG0 + gb + 2 * sub;
                #pragma unroll 3
                for (int i = 0; i < reps; i++) {
                    __stcs((float2*)p, v);
                    p += stride;
                }
            }
        }
    }
}

// ---------------------------------------------------------------------------
extern "C" void kernel_launch(void* const* d_in, const int* in_sizes, int n_in,
                              void* d_out, int out_size) {
    const float* A    = (const float*)d_in[0];  // (128, 2048)
    const float* st   = (const float*)d_in[1];  // (1500,)
    const float* init = (const float*)d_in[2];  // (128, 250)
    int off = (n_in >= 8) ? 1 : 0;              // skip n_repeats scalar if present
    const float* sf = (const float*)d_in[3 + off];  // (2048,)
    const float* tf = (const float*)d_in[4 + off];  // (250,)
    const float* fb = (const float*)d_in[5 + off];  // (250,)
    const float* bi = (const float*)d_in[6 + off];  // (1,)

    k_all<<<B, 1024>>>(A, st, init, sf, tf, fb, bi, (float*)d_out);
}

// round 11
// speedup vs baseline: 1.7232x; 1.1755x over previous
#include <cuda_runtime.h>

// Problem constants (fixed by setup_inputs)
#define B     128
#define NPIX  2048
#define NBINS 1500
#define NBF   250
#define NREP  256
#define TSIM  1250   // len_bins_sim
#define NBLK  40     // ceil(TSIM/32)
#define N1    ((size_t)B * NREP * NBINS)   // start of gensig region in d_out

#define NLOG2E (-1.4426950408889634f)
#define LN2    (0.6931471805599453f)
#define NCW    30    // copy warps per CTA
#define CSEG   8     // segments per copy chunk (5 chunks of 8)
#define NCHK   5

__device__ __forceinline__ float fex2(float x) {
    float r; asm("ex2.approx.ftz.f32 %0, %1;" : "=f"(r) : "f"(x)); return r;
}
__device__ __forceinline__ float frcp(float x) {
    float r; asm("rcp.approx.ftz.f32 %0, %1;" : "=f"(r) : "f"(x)); return r;
}

// ---------------------------------------------------------------------------
// ONE kernel, 128 CTAs x 1024 threads (one CTA per batch):
//   setup     : all warps — filters, spatial dot, 1250-pt correlation, drive
//   warp 31   : serial z-space chain, 32 steps/iteration, publishes progress
//   warp 30   : pipelined precompute of next block's history-only partials
//   warps 0-29: CHUNKED broadcast — wait for 8 finished segments, then write
//               1KB contiguous spans per output row (first chunk: 2KB with the
//               init section merged). Large contiguous spans restore DRAM page
//               locality (the per-segment 128B writes of earlier rounds were
//               capped at ~2.1 TB/s by page activation overhead).
//
// Timeline coords: tl[k]=init[k] for k<250, tl[250+t]=spike_t.
// fb_t = sum_{j=0..249} tl[t+j] * f[j].
// For block at T0, lane i (t=T0+i):
//   - taps j in [0, 217-i]   : spikes through block m-2 -> warp-30 precompute
//   - taps j in [218-i,249-i]: block m-1 spikes         -> 32-tap fixup
//   - taps j in [250-i,249]  : in-block spikes          -> serial shfl chain
// ---------------------------------------------------------------------------
__global__ __launch_bounds__(1024, 1) void k_all(
    const float* __restrict__ A,    // (128, 2048)
    const float* __restrict__ st,   // (1500,)
    const float* __restrict__ init, // (128, 250)
    const float* __restrict__ sf,   // (2048,)
    const float* __restrict__ tf,   // (250,)
    const float* __restrict__ fbf,  // (250,)
    const float* __restrict__ bias, // (1,)
    float* __restrict__ out)
{
    __shared__ __align__(16) float sh_tl[1504];   // timeline (init + spikes)
    __shared__ __align__(16) float sh_f[288];     // feedback filter, zero-padded
    __shared__ __align__(16) float sh_fw[288];    // -log2e * filter
    __shared__ __align__(16) float sh_g[1280];    // drive; overwritten w/ gensig
    __shared__ __align__(16) float sh_tc[256];    // timecourse filter
    __shared__ __align__(16) float sh_st[1504];   // stim_time
    __shared__ float red[512];
    __shared__ float sh_pre[2][32];
    __shared__ int   sh_prog;                     // segments produced (0..NBLK)

    int b = blockIdx.x, tid = threadIdx.x;
    int warp = tid >> 5, lane = tid & 31;
    float* outG = out + N1;

    // ------------------------- setup -------------------------
    if (tid == 0) sh_prog = 0;
    if (tid < NBF) {
        sh_f[tid]  = fbf[tid];
        sh_tc[tid] = tf[tid];
        sh_tl[tid] = init[b * NBF + tid];
    } else if (tid < 288) sh_f[tid] = 0.f;
    if (tid < NBINS) sh_st[tid] = st[tid];
    if (tid + 1024 < NBINS) sh_st[tid + 1024] = st[tid + 1024];
    if (tid < 512) {   // spatial dot partials (one float4 per thread)
        const float4* row4 = (const float4*)(A + (size_t)b * NPIX);
        const float4* sf4  = (const float4*)sf;
        float4 a = row4[tid], f = sf4[tid];
        red[tid] = a.x*f.x + a.y*f.y + a.z*f.z + a.w*f.w;
    }
    __syncthreads();

    if (tid < 288) sh_fw[tid] = NLOG2E * sh_f[tid];
    if (warp == 0) {   // reduce spatial dot
        float r = 0.f;
        #pragma unroll
        for (int k = 0; k < 16; k++) r += red[lane + 32 * k];
        #pragma unroll
        for (int o = 16; o > 0; o >>= 1) r += __shfl_xor_sync(0xffffffffu, r, o);
        if (lane == 0) red[0] = r;
    }
    // correlation: 2 t-values per thread (t = tid, tid + 1024)
    float c0 = 0.f, c1 = 0.f;
    {
        int t0 = tid, t1 = tid + 1024;
        float a0 = 0, a1 = 0, a2 = 0, a3 = 0;
        for (int j = 0; j < 248; j += 4) {
            a0 = fmaf(sh_st[t0 + j],     sh_tc[j],     a0);
            a1 = fmaf(sh_st[t0 + j + 1], sh_tc[j + 1], a1);
            a2 = fmaf(sh_st[t0 + j + 2], sh_tc[j + 2], a2);
            a3 = fmaf(sh_st[t0 + j + 3], sh_tc[j + 3], a3);
        }
        a0 = fmaf(sh_st[t0 + 248], sh_tc[248], a0);
        a1 = fmaf(sh_st[t0 + 249], sh_tc[249], a1);
        c0 = (a0 + a1) + (a2 + a3);
        if (t1 < TSIM) {
            float b0 = 0, b1 = 0, b2 = 0, b3 = 0;
            for (int j = 0; j < 248; j += 4) {
                b0 = fmaf(sh_st[t1 + j],     sh_tc[j],     b0);
                b1 = fmaf(sh_st[t1 + j + 1], sh_tc[j + 1], b1);
                b2 = fmaf(sh_st[t1 + j + 2], sh_tc[j + 2], b2);
                b3 = fmaf(sh_st[t1 + j + 3], sh_tc[j + 3], b3);
            }
            b0 = fmaf(sh_st[t1 + 248], sh_tc[248], b0);
            b1 = fmaf(sh_st[t1 + 249], sh_tc[249], b1);
            c1 = (b0 + b1) + (b2 + b3);
        }
    }
    __syncthreads();
    {
        float fs = red[0], bv = bias[0];
        sh_g[tid] = (tid < TSIM) ? fmaf(fs, c0, bv) : 0.f;
        if (tid + 1024 < 1280)
            sh_g[tid + 1024] = (tid + 1024 < TSIM) ? fmaf(fs, c1, bv) : 0.f;
    }
    __syncthreads();

    // ------------------------- role split -------------------------
    if (warp == 31) {
        // ---------------- serial chain (z-space) ----------------
        {   // block-0 precompute: all taps from initial history
            int lim = 250 - lane;
            float a0 = 0, a1 = 0, a2 = 0, a3 = 0;
            int j = 0;
            for (; j + 4 <= lim; j += 4) {
                a0 = fmaf(sh_tl[lane + j],     sh_f[j],     a0);
                a1 = fmaf(sh_tl[lane + j + 1], sh_f[j + 1], a1);
                a2 = fmaf(sh_tl[lane + j + 2], sh_f[j + 2], a2);
                a3 = fmaf(sh_tl[lane + j + 3], sh_f[j + 3], a3);
            }
            for (; j < lim; j++) a0 = fmaf(sh_tl[lane + j], sh_f[j], a0);
            sh_pre[0][lane] = (a0 + a1) + (a2 + a3);
        }
        int fchain = 250 - lane;   // chain tap base (sh_fw)
        int ffix   = 218 - lane;   // fixup tap base (sh_f)

        for (int m = 0; m < NBLK; m++) {
            asm volatile("bar.sync 1, 64;" ::: "memory");  // warps 30+31 only
            int T0 = m * 32, t = T0 + lane;
            float part = sh_pre[m & 1][lane] + sh_g[t];

            if (m > 0) {   // fixup: previous block's 32 spikes
                int base = 250 + T0 - 32;
                float a0 = 0, a1 = 0, a2 = 0, a3 = 0;
                #pragma unroll
                for (int k = 0; k < 32; k += 4) {
                    a0 = fmaf(sh_tl[base + k],     sh_f[ffix + k],     a0);
                    a1 = fmaf(sh_tl[base + k + 1], sh_f[ffix + k + 1], a1);
                    a2 = fmaf(sh_tl[base + k + 2], sh_f[ffix + k + 2], a2);
                    a3 = fmaf(sh_tl[base + k + 3], sh_f[ffix + k + 3], a3);
                }
                part += (a0 + a1) + (a2 + a3);
            }

            // z-space chain: sigmoid = rcp(1 + 2^z), z = -log2e * gensig.
            // sh_fw[fchain+k]==0 for k>=lane, so each lane's z freezes at its
            // own step; sl after the loop = sigmoid of the frozen gensig.
            float z = NLOG2E * part;
            float sl = 0.f;
            #pragma unroll
            for (int k = 0; k < 32; k++) {
                float e = fex2(z);
                sl = frcp(1.0f + e);
                float s = __shfl_sync(0xffffffffu, sl, k);
                z = fmaf(s, sh_fw[fchain + k], z);
            }

            int kmax = TSIM - T0; if (kmax > 32) kmax = 32;
            if (lane < kmax) {
                sh_tl[250 + t] = sl;          // spike_t
                sh_g[t] = -LN2 * z;           // gensig_t
            }
            __syncwarp();
            if (lane == 0) { __threadfence_block(); *(volatile int*)&sh_prog = m + 1; }
        }
    } else if (warp == 30) {
        // ---------------- pipelined precompute ----------------
        for (int m = 0; m < NBLK; m++) {
            asm volatile("bar.sync 1, 64;" ::: "memory");
            if (m + 1 < NBLK) {   // block m+1 partials over spikes through m-1
                int T0n = m * 32 + 32;
                int lim = 218 - lane;
                float a0 = 0, a1 = 0, a2 = 0, a3 = 0;
                int j = 0;
                for (; j + 4 <= lim; j += 4) {
                    a0 = fmaf(sh_tl[T0n + lane + j],     sh_f[j],     a0);
                    a1 = fmaf(sh_tl[T0n + lane + j + 1], sh_f[j + 1], a1);
                    a2 = fmaf(sh_tl[T0n + lane + j + 2], sh_f[j + 2], a2);
                    a3 = fmaf(sh_tl[T0n + lane + j + 3], sh_f[j + 3], a3);
                }
                for (; j < lim; j++) a0 = fmaf(sh_tl[T0n + lane + j], sh_f[j], a0);
                sh_pre[(m + 1) & 1][lane] = (a0 + a1) + (a2 + a3);
            }
        }
    } else {
        // --------- chunked copy warps 0..29: all 256 repeats ---------
        volatile int* prog = &sh_prog;
        const float2* stl2 = (const float2*)sh_tl;
        const float2* sg2  = (const float2*)sh_g;

        for (int c = 0; c < NCHK; c++) {
            int need = CSEG * (c + 1);                 // segments required
            while (*prog < need) __nanosleep(64);
            __threadfence_block();

            // timeline float2 range for this chunk (c==0 merges init section)
            int tlo = (c == 0) ? 0 : 125 + 128 * c;    // float2 index
            int thi = 125 + 128 * (c + 1); if (thi > 750) thi = 750;
            // gensig float2 range
            int glo = 128 * c;
            int ghi = 128 * (c + 1); if (ghi > 625) ghi = 625;

            for (int r = warp; r < NREP; r += NCW) {
                size_t row = (size_t)(b * NREP + r);
                float2* dT = (float2*)(out + row * NBINS);
                float2* dG = (float2*)(outG + row * TSIM);
                for (int i = tlo + lane; i < thi; i += 32) __stcs(dT + i, stl2[i]);
                for (int i = glo + lane; i < ghi; i += 32) __stcs(dG + i, sg2[i]);
            }
        }
    }
}

// ---------------------------------------------------------------------------
extern "C" void kernel_launch(void* const* d_in, const int* in_sizes, int n_in,
                              void* d_out, int out_size) {
    const float* A    = (const float*)d_in[0];  // (128, 2048)
    const float* st   = (const float*)d_in[1];  // (1500,)
    const float* init = (const float*)d_in[2];  // (128, 250)
    int off = (n_in >= 8) ? 1 : 0;              // skip n_repeats scalar if present
    const float* sf = (const float*)d_in[3 + off];  // (2048,)
    const float* tf = (const float*)d_in[4 + off];  // (250,)
    const float* fb = (const float*)d_in[5 + off];  // (250,)
    const float* bi = (const float*)d_in[6 + off];  // (1,)

    k_all<<<B, 1024>>>(A, st, init, sf, tf, fb, bi, (float*)d_out);
}

// round 12
// speedup vs baseline: 1.7594x; 1.0210x over previous
#include <cuda_runtime.h>

// Problem constants (fixed by setup_inputs)
#define B     128
#define NPIX  2048
#define NBINS 1500
#define NBF   250
#define NREP  256
#define TSIM  1250   // len_bins_sim
#define NBLK  40     // ceil(TSIM/32)
#define N1    ((size_t)B * NREP * NBINS)   // start of gensig region in d_out

#define NCW    30    // copy warps per CTA
#define CSEG   8     // segments per copy chunk (5 chunks of 8)
#define NCHK   5

__device__ __forceinline__ float ftanh(float x) {
    float r; asm("tanh.approx.f32 %0, %1;" : "=f"(r) : "f"(x)); return r;
}

// ---------------------------------------------------------------------------
// ONE kernel, 128 CTAs x 1024 threads (one CTA per batch):
//   setup     : all warps — filters, spatial dot, 1250-pt correlation, drive
//   warp 31   : serial chain via tanh identity, 32 steps/iteration.
//               sigmoid(g) = 0.5 + 0.5*tanh(g/2); with s_k = 0.5 + 0.5*t_k the
//               constant halves fold into a per-lane precomputed constant, so
//               the serial path is Y -> TANH(16) -> SHFL(26) -> FMA(4) = 46cyc
//   warp 30   : pipelined precompute of next block's history-only partials
//   warps 0-29: CHUNKED broadcast — wait for 8 finished segments, then write
//               ~1KB contiguous spans per output row. No consumer-side
//               membars (producer's fence before the flag store suffices).
//
// Timeline coords: tl[k]=init[k] for k<250, tl[250+t]=spike_t.
// fb_t = sum_{j=0..249} tl[t+j] * f[j].
// For block at T0, lane i (t=T0+i):
//   - taps j in [0, 217-i]   : spikes through block m-2 -> warp-30 precompute
//   - taps j in [218-i,249-i]: block m-1 spikes         -> 32-tap fixup
//   - taps j in [250-i,249]  : in-block spikes          -> serial shfl chain
// ---------------------------------------------------------------------------
__global__ __launch_bounds__(1024, 1) void k_all(
    const float* __restrict__ A,    // (128, 2048)
    const float* __restrict__ st,   // (1500,)
    const float* __restrict__ init, // (128, 250)
    const float* __restrict__ sf,   // (2048,)
    const float* __restrict__ tf,   // (250,)
    const float* __restrict__ fbf,  // (250,)
    const float* __restrict__ bias, // (1,)
    float* __restrict__ out)
{
    __shared__ __align__(16) float sh_tl[1504];   // timeline (init + spikes)
    __shared__ __align__(16) float sh_f[288];     // feedback filter, zero-padded
    __shared__ __align__(16) float sh_fq[288];    // 0.25 * filter (chain taps)
    __shared__ __align__(16) float sh_g[1280];    // drive; overwritten w/ gensig
    __shared__ __align__(16) float sh_tc[256];    // timecourse filter
    __shared__ __align__(16) float sh_st[1504];   // stim_time
    __shared__ float red[512];
    __shared__ float sh_pre[2][32];
    __shared__ int   sh_prog;                     // segments produced (0..NBLK)

    int b = blockIdx.x, tid = threadIdx.x;
    int warp = tid >> 5, lane = tid & 31;
    float* outG = out + N1;

    // ------------------------- setup -------------------------
    if (tid == 0) sh_prog = 0;
    if (tid < NBF) {
        sh_f[tid]  = fbf[tid];
        sh_tc[tid] = tf[tid];
        sh_tl[tid] = init[b * NBF + tid];
    } else if (tid < 288) sh_f[tid] = 0.f;
    if (tid < NBINS) sh_st[tid] = st[tid];
    if (tid + 1024 < NBINS) sh_st[tid + 1024] = st[tid + 1024];
    if (tid < 512) {   // spatial dot partials (one float4 per thread)
        const float4* row4 = (const float4*)(A + (size_t)b * NPIX);
        const float4* sf4  = (const float4*)sf;
        float4 a = row4[tid], f = sf4[tid];
        red[tid] = a.x*f.x + a.y*f.y + a.z*f.z + a.w*f.w;
    }
    __syncthreads();

    if (tid < 288) sh_fq[tid] = 0.25f * sh_f[tid];
    if (warp == 0) {   // reduce spatial dot
        float r = 0.f;
        #pragma unroll
        for (int k = 0; k < 16; k++) r += red[lane + 32 * k];
        #pragma unroll
        for (int o = 16; o > 0; o >>= 1) r += __shfl_xor_sync(0xffffffffu, r, o);
        if (lane == 0) red[0] = r;
    }
    // correlation: 2 t-values per thread (t = tid, tid + 1024)
    float c0 = 0.f, c1 = 0.f;
    {
        int t0 = tid, t1 = tid + 1024;
        float a0 = 0, a1 = 0, a2 = 0, a3 = 0;
        for (int j = 0; j < 248; j += 4) {
            a0 = fmaf(sh_st[t0 + j],     sh_tc[j],     a0);
            a1 = fmaf(sh_st[t0 + j + 1], sh_tc[j + 1], a1);
            a2 = fmaf(sh_st[t0 + j + 2], sh_tc[j + 2], a2);
            a3 = fmaf(sh_st[t0 + j + 3], sh_tc[j + 3], a3);
        }
        a0 = fmaf(sh_st[t0 + 248], sh_tc[248], a0);
        a1 = fmaf(sh_st[t0 + 249], sh_tc[249], a1);
        c0 = (a0 + a1) + (a2 + a3);
        if (t1 < TSIM) {
            float b0 = 0, b1 = 0, b2 = 0, b3 = 0;
            for (int j = 0; j < 248; j += 4) {
                b0 = fmaf(sh_st[t1 + j],     sh_tc[j],     b0);
                b1 = fmaf(sh_st[t1 + j + 1], sh_tc[j + 1], b1);
                b2 = fmaf(sh_st[t1 + j + 2], sh_tc[j + 2], b2);
                b3 = fmaf(sh_st[t1 + j + 3], sh_tc[j + 3], b3);
            }
            b0 = fmaf(sh_st[t1 + 248], sh_tc[248], b0);
            b1 = fmaf(sh_st[t1 + 249], sh_tc[249], b1);
            c1 = (b0 + b1) + (b2 + b3);
        }
    }
    __syncthreads();
    {
        float fs = red[0], bv = bias[0];
        sh_g[tid] = (tid < TSIM) ? fmaf(fs, c0, bv) : 0.f;
        if (tid + 1024 < 1280)
            sh_g[tid + 1024] = (tid + 1024 < TSIM) ? fmaf(fs, c1, bv) : 0.f;
    }
    __syncthreads();

    // ------------------------- role split -------------------------
    if (warp == 31) {
        // ---------------- serial chain (tanh form) ----------------
        {   // block-0 precompute: all taps from initial history
            int lim = 250 - lane;
            float a0 = 0, a1 = 0, a2 = 0, a3 = 0;
            int j = 0;
            for (; j + 4 <= lim; j += 4) {
                a0 = fmaf(sh_tl[lane + j],     sh_f[j],     a0);
                a1 = fmaf(sh_tl[lane + j + 1], sh_f[j + 1], a1);
                a2 = fmaf(sh_tl[lane + j + 2], sh_f[j + 2], a2);
                a3 = fmaf(sh_tl[lane + j + 3], sh_f[j + 3], a3);
            }
            for (; j < lim; j++) a0 = fmaf(sh_tl[lane + j], sh_f[j], a0);
            sh_pre[0][lane] = (a0 + a1) + (a2 + a3);
        }
        int fchain = 250 - lane;   // chain tap base (sh_fq)
        int ffix   = 218 - lane;   // fixup tap base (sh_f)

        // per-lane constant: C = 0.25 * sum_k F_ik  (zeros pad k >= lane)
        float Ci = 0.f;
        #pragma unroll
        for (int k = 0; k < 32; k++) Ci += sh_fq[fchain + k];

        for (int m = 0; m < NBLK; m++) {
            asm volatile("bar.sync 1, 64;" ::: "memory");  // warps 30+31 only
            int T0 = m * 32, t = T0 + lane;
            float part = sh_pre[m & 1][lane] + sh_g[t];

            if (m > 0) {   // fixup: previous block's 32 spikes
                int base = 250 + T0 - 32;
                float a0 = 0, a1 = 0, a2 = 0, a3 = 0;
                #pragma unroll
                for (int k = 0; k < 32; k += 4) {
                    a0 = fmaf(sh_tl[base + k],     sh_f[ffix + k],     a0);
                    a1 = fmaf(sh_tl[base + k + 1], sh_f[ffix + k + 1], a1);
                    a2 = fmaf(sh_tl[base + k + 2], sh_f[ffix + k + 2], a2);
                    a3 = fmaf(sh_tl[base + k + 3], sh_f[ffix + k + 3], a3);
                }
                part += (a0 + a1) + (a2 + a3);
            }

            // Y = gensig/2 including folded 0.5-halves of future in-block
            // spikes: Y = 0.5*part + C. Chain: Y += t_k * (0.25*F_ik).
            // sh_fq taps are zero for k >= lane, so each lane's Y freezes at
            // its own step; after the loop tl = tanh(final Y) for every lane.
            float Y = fmaf(0.5f, part, Ci);
            float tl = 0.f;
            #pragma unroll
            for (int k = 0; k < 32; k++) {
                tl = ftanh(Y);
                float s = __shfl_sync(0xffffffffu, tl, k);
                Y = fmaf(s, sh_fq[fchain + k], Y);
            }

            int kmax = TSIM - T0; if (kmax > 32) kmax = 32;
            if (lane < kmax) {
                sh_tl[250 + t] = fmaf(0.5f, tl, 0.5f);   // spike = sigmoid(g)
                sh_g[t] = 2.0f * Y;                      // gensig
            }
            __syncwarp();
            if (lane == 0) { __threadfence_block(); *(volatile int*)&sh_prog = m + 1; }
        }
    } else if (warp == 30) {
        // ---------------- pipelined precompute ----------------
        for (int m = 0; m < NBLK; m++) {
            asm volatile("bar.sync 1, 64;" ::: "memory");
            if (m + 1 < NBLK) {   // block m+1 partials over spikes through m-1
                int T0n = m * 32 + 32;
                int lim = 218 - lane;
                float a0 = 0, a1 = 0, a2 = 0, a3 = 0;
                int j = 0;
                for (; j + 4 <= lim; j += 4) {
                    a0 = fmaf(sh_tl[T0n + lane + j],     sh_f[j],     a0);
                    a1 = fmaf(sh_tl[T0n + lane + j + 1], sh_f[j + 1], a1);
                    a2 = fmaf(sh_tl[T0n + lane + j + 2], sh_f[j + 2], a2);
                    a3 = fmaf(sh_tl[T0n + lane + j + 3], sh_f[j + 3], a3);
                }
                for (; j < lim; j++) a0 = fmaf(sh_tl[T0n + lane + j], sh_f[j], a0);
                sh_pre[(m + 1) & 1][lane] = (a0 + a1) + (a2 + a3);
            }
        }
    } else {
        // --------- chunked copy warps 0..29: all 256 repeats ---------
        volatile int* prog = &sh_prog;
        const float2* stl2 = (const float2*)sh_tl;
        const float2* sg2  = (const float2*)sh_g;

        for (int c = 0; c < NCHK; c++) {
            int need = CSEG * (c + 1);                 // segments required
            while (*prog < need) __nanosleep(64);
            // no consumer fence needed: producer's __threadfence_block before
            // the flag store orders spike/gensig STS ahead of the flag, and
            // shared-memory loads after the flag load cannot see stale data.

            // timeline float2 range for this chunk (c==0 merges init section)
            int tlo = (c == 0) ? 0 : 125 + 128 * c;    // float2 index
            int thi = 125 + 128 * (c + 1); if (thi > 750) thi = 750;
            // gensig float2 range
            int glo = 128 * c;
            int ghi = 128 * (c + 1); if (ghi > 625) ghi = 625;

            for (int r = warp; r < NREP; r += NCW) {
                size_t row = (size_t)(b * NREP + r);
                float2* dT = (float2*)(out + row * NBINS);
                float2* dG = (float2*)(outG + row * TSIM);
                for (int i = tlo + lane; i < thi; i += 32) __stcs(dT + i, stl2[i]);
                for (int i = glo + lane; i < ghi; i += 32) __stcs(dG + i, sg2[i]);
            }
        }
    }
}

// ---------------------------------------------------------------------------
extern "C" void kernel_launch(void* const* d_in, const int* in_sizes, int n_in,
                              void* d_out, int out_size) {
    const float* A    = (const float*)d_in[0];  // (128, 2048)
    const float* st   = (const float*)d_in[1];  // (1500,)
    const float* init = (const float*)d_in[2];  // (128, 250)
    int off = (n_in >= 8) ? 1 : 0;              // skip n_repeats scalar if present
    const float* sf = (const float*)d_in[3 + off];  // (2048,)
    const float* tf = (const float*)d_in[4 + off];  // (250,)
    const float* fb = (const float*)d_in[5 + off];  // (250,)
    const float* bi = (const float*)d_in[6 + off];  // (1,)

    k_all<<<B, 1024>>>(A, st, init, sf, tf, fb, bi, (float*)d_out);
}

// round 13
// speedup vs baseline: 1.7602x; 1.0005x over previous
#include <cuda_runtime.h>

// Problem constants (fixed by setup_inputs)
#define B     128
#define NPIX  2048
#define NBINS 1500
#define NBF   250
#define NREP  256
#define TSIM  1250   // len_bins_sim
#define NBLK  40     // ceil(TSIM/32)
#define N1    ((size_t)B * NREP * NBINS)   // start of gensig region in d_out

#define NCW    30    // copy warps per CTA
#define CSEG   8     // segments per copy chunk (5 chunks of 8)
#define NCHK   5

__device__ __forceinline__ float ftanh(float x) {
    float r; asm("tanh.approx.f32 %0, %1;" : "=f"(r) : "f"(x)); return r;
}

// ---------------------------------------------------------------------------
// ONE kernel, 128 CTAs x 1024 threads (one CTA per batch):
//   setup     : all warps — filters, spatial dot, 1250-pt correlation, drive
//   warp 31   : serial chain via tanh identity, 32 steps/iteration
//               (sigmoid(g) = 0.5 + 0.5*tanh(g/2), halves folded into a
//               per-lane constant; serial path = TANH->SHFL->FMA = 46 cyc)
//   warp 30   : pipelined precompute of next block's history-only partials
//   warps 0-29: REGISTER-RESIDENT chunked broadcast. Each warp loads its
//               chunk span from shared into registers ONCE, then the per-row
//               loop is pure STG.64 (~12 stores / 2KB row-span). This removes
//               the per-row LDS + loop overhead that made the copy path
//               issue-bound (~1M warp-instrs/CTA -> ~170k).
//
// Timeline coords: tl[k]=init[k] for k<250, tl[250+t]=spike_t.
// fb_t = sum_{j=0..249} tl[t+j] * f[j].
// For block at T0, lane i (t=T0+i):
//   - taps j in [0, 217-i]   : spikes through block m-2 -> warp-30 precompute
//   - taps j in [218-i,249-i]: block m-1 spikes         -> 32-tap fixup
//   - taps j in [250-i,249]  : in-block spikes          -> serial shfl chain
// ---------------------------------------------------------------------------
__global__ __launch_bounds__(1024, 1) void k_all(
    const float* __restrict__ A,    // (128, 2048)
    const float* __restrict__ st,   // (1500,)
    const float* __restrict__ init, // (128, 250)
    const float* __restrict__ sf,   // (2048,)
    const float* __restrict__ tf,   // (250,)
    const float* __restrict__ fbf,  // (250,)
    const float* __restrict__ bias, // (1,)
    float* __restrict__ out)
{
    __shared__ __align__(16) float sh_tl[1504];   // timeline (init + spikes)
    __shared__ __align__(16) float sh_f[288];     // feedback filter, zero-padded
    __shared__ __align__(16) float sh_fq[288];    // 0.25 * filter (chain taps)
    __shared__ __align__(16) float sh_g[1280];    // drive; overwritten w/ gensig
    __shared__ __align__(16) float sh_tc[256];    // timecourse filter
    __shared__ __align__(16) float sh_st[1504];   // stim_time
    __shared__ float red[512];
    __shared__ float sh_pre[2][32];
    __shared__ int   sh_prog;                     // segments produced (0..NBLK)

    int b = blockIdx.x, tid = threadIdx.x;
    int warp = tid >> 5, lane = tid & 31;
    float* outG = out + N1;

    // ------------------------- setup -------------------------
    if (tid == 0) sh_prog = 0;
    if (tid < NBF) {
        sh_f[tid]  = fbf[tid];
        sh_tc[tid] = tf[tid];
        sh_tl[tid] = init[b * NBF + tid];
    } else if (tid < 288) sh_f[tid] = 0.f;
    if (tid < NBINS) sh_st[tid] = st[tid];
    if (tid + 1024 < NBINS) sh_st[tid + 1024] = st[tid + 1024];
    if (tid < 512) {   // spatial dot partials (one float4 per thread)
        const float4* row4 = (const float4*)(A + (size_t)b * NPIX);
        const float4* sf4  = (const float4*)sf;
        float4 a = row4[tid], f = sf4[tid];
        red[tid] = a.x*f.x + a.y*f.y + a.z*f.z + a.w*f.w;
    }
    __syncthreads();

    if (tid < 288) sh_fq[tid] = 0.25f * sh_f[tid];
    if (warp == 0) {   // reduce spatial dot
        float r = 0.f;
        #pragma unroll
        for (int k = 0; k < 16; k++) r += red[lane + 32 * k];
        #pragma unroll
        for (int o = 16; o > 0; o >>= 1) r += __shfl_xor_sync(0xffffffffu, r, o);
        if (lane == 0) red[0] = r;
    }
    // correlation: 2 t-values per thread (t = tid, tid + 1024)
    float c0 = 0.f, c1 = 0.f;
    {
        int t0 = tid, t1 = tid + 1024;
        float a0 = 0, a1 = 0, a2 = 0, a3 = 0;
        for (int j = 0; j < 248; j += 4) {
            a0 = fmaf(sh_st[t0 + j],     sh_tc[j],     a0);
            a1 = fmaf(sh_st[t0 + j + 1], sh_tc[j + 1], a1);
            a2 = fmaf(sh_st[t0 + j + 2], sh_tc[j + 2], a2);
            a3 = fmaf(sh_st[t0 + j + 3], sh_tc[j + 3], a3);
        }
        a0 = fmaf(sh_st[t0 + 248], sh_tc[248], a0);
        a1 = fmaf(sh_st[t0 + 249], sh_tc[249], a1);
        c0 = (a0 + a1) + (a2 + a3);
        if (t1 < TSIM) {
            float b0 = 0, b1 = 0, b2 = 0, b3 = 0;
            for (int j = 0; j < 248; j += 4) {
                b0 = fmaf(sh_st[t1 + j],     sh_tc[j],     b0);
                b1 = fmaf(sh_st[t1 + j + 1], sh_tc[j + 1], b1);
                b2 = fmaf(sh_st[t1 + j + 2], sh_tc[j + 2], b2);
                b3 = fmaf(sh_st[t1 + j + 3], sh_tc[j + 3], b3);
            }
            b0 = fmaf(sh_st[t1 + 248], sh_tc[248], b0);
            b1 = fmaf(sh_st[t1 + 249], sh_tc[249], b1);
            c1 = (b0 + b1) + (b2 + b3);
        }
    }
    __syncthreads();
    {
        float fs = red[0], bv = bias[0];
        sh_g[tid] = (tid < TSIM) ? fmaf(fs, c0, bv) : 0.f;
        if (tid + 1024 < 1280)
            sh_g[tid + 1024] = (tid + 1024 < TSIM) ? fmaf(fs, c1, bv) : 0.f;
    }
    __syncthreads();

    // ------------------------- role split -------------------------
    if (warp == 31) {
        // ---------------- serial chain (tanh form) ----------------
        {   // block-0 precompute: all taps from initial history
            int lim = 250 - lane;
            float a0 = 0, a1 = 0, a2 = 0, a3 = 0;
            int j = 0;
            for (; j + 4 <= lim; j += 4) {
                a0 = fmaf(sh_tl[lane + j],     sh_f[j],     a0);
                a1 = fmaf(sh_tl[lane + j + 1], sh_f[j + 1], a1);
                a2 = fmaf(sh_tl[lane + j + 2], sh_f[j + 2], a2);
                a3 = fmaf(sh_tl[lane + j + 3], sh_f[j + 3], a3);
            }
            for (; j < lim; j++) a0 = fmaf(sh_tl[lane + j], sh_f[j], a0);
            sh_pre[0][lane] = (a0 + a1) + (a2 + a3);
        }
        int fchain = 250 - lane;   // chain tap base (sh_fq)
        int ffix   = 218 - lane;   // fixup tap base (sh_f)

        // per-lane constant: C = 0.25 * sum_k F_ik  (zeros pad k >= lane)
        float Ci = 0.f;
        #pragma unroll
        for (int k = 0; k < 32; k++) Ci += sh_fq[fchain + k];

        for (int m = 0; m < NBLK; m++) {
            asm volatile("bar.sync 1, 64;" ::: "memory");  // warps 30+31 only
            int T0 = m * 32, t = T0 + lane;
            float part = sh_pre[m & 1][lane] + sh_g[t];

            if (m > 0) {   // fixup: previous block's 32 spikes
                int base = 250 + T0 - 32;
                float a0 = 0, a1 = 0, a2 = 0, a3 = 0;
                #pragma unroll
                for (int k = 0; k < 32; k += 4) {
                    a0 = fmaf(sh_tl[base + k],     sh_f[ffix + k],     a0);
                    a1 = fmaf(sh_tl[base + k + 1], sh_f[ffix + k + 1], a1);
                    a2 = fmaf(sh_tl[base + k + 2], sh_f[ffix + k + 2], a2);
                    a3 = fmaf(sh_tl[base + k + 3], sh_f[ffix + k + 3], a3);
                }
                part += (a0 + a1) + (a2 + a3);
            }

            // Y = gensig/2 with folded halves: Y = 0.5*part + C.
            // Chain: Y += t_k * (0.25*F_ik); taps zero for k >= lane so each
            // lane's Y freezes at its own step; tl = tanh(final Y).
            float Y = fmaf(0.5f, part, Ci);
            float tl = 0.f;
            #pragma unroll
            for (int k = 0; k < 32; k++) {
                tl = ftanh(Y);
                float s = __shfl_sync(0xffffffffu, tl, k);
                Y = fmaf(s, sh_fq[fchain + k], Y);
            }

            int kmax = TSIM - T0; if (kmax > 32) kmax = 32;
            if (lane < kmax) {
                sh_tl[250 + t] = fmaf(0.5f, tl, 0.5f);   // spike = sigmoid(g)
                sh_g[t] = 2.0f * Y;                      // gensig
            }
            __syncwarp();
            if (lane == 0) { __threadfence_block(); *(volatile int*)&sh_prog = m + 1; }
        }
    } else if (warp == 30) {
        // ---------------- pipelined precompute ----------------
        for (int m = 0; m < NBLK; m++) {
            asm volatile("bar.sync 1, 64;" ::: "memory");
            if (m + 1 < NBLK) {   // block m+1 partials over spikes through m-1
                int T0n = m * 32 + 32;
                int lim = 218 - lane;
                float a0 = 0, a1 = 0, a2 = 0, a3 = 0;
                int j = 0;
                for (; j + 4 <= lim; j += 4) {
                    a0 = fmaf(sh_tl[T0n + lane + j],     sh_f[j],     a0);
                    a1 = fmaf(sh_tl[T0n + lane + j + 1], sh_f[j + 1], a1);
                    a2 = fmaf(sh_tl[T0n + lane + j + 2], sh_f[j + 2], a2);
                    a3 = fmaf(sh_tl[T0n + lane + j + 3], sh_f[j + 3], a3);
                }
                for (; j < lim; j++) a0 = fmaf(sh_tl[T0n + lane + j], sh_f[j], a0);
                sh_pre[(m + 1) & 1][lane] = (a0 + a1) + (a2 + a3);
            }
        }
    } else {
        // --- register-resident chunked copy warps 0..29: all 256 repeats ---
        volatile int* prog = &sh_prog;
        const float2* stl2 = (const float2*)sh_tl;
        const float2* sg2  = (const float2*)sh_g;

        for (int c = 0; c < NCHK; c++) {
            while (*prog < CSEG * (c + 1)) __nanosleep(64);
            // producer's __threadfence_block before the flag store orders the
            // spike/gensig STS ahead of the flag; no consumer fence needed.

            // timeline float2 range (c==0 merges the 250-float init section)
            int tlo = (c == 0) ? 0 : 125 + 128 * c;
            int thi = 125 + 128 * (c + 1); if (thi > 750) thi = 750;
            // gensig float2 range
            int glo = 128 * c;
            int ghi = 128 * (c + 1); if (ghi > 625) ghi = 625;

            // load spans into registers ONCE per chunk
            float2 tl_r[8], g_r[4];
            #pragma unroll
            for (int u = 0; u < 8; u++) {
                int i = tlo + lane + 32 * u;
                if (i < thi) tl_r[u] = stl2[i];
            }
            #pragma unroll
            for (int u = 0; u < 4; u++) {
                int i = glo + lane + 32 * u;
                if (i < ghi) g_r[u] = sg2[i];
            }

            // per-row loop: pure stores
            for (int r = warp; r < NREP; r += NCW) {
                size_t row = (size_t)(b * NREP + r);
                float2* dT = (float2*)(out + row * NBINS);
                float2* dG = (float2*)(outG + row * TSIM);
                #pragma unroll
                for (int u = 0; u < 8; u++) {
                    int i = tlo + lane + 32 * u;
                    if (i < thi) __stcs(dT + i, tl_r[u]);
                }
                #pragma unroll
                for (int u = 0; u < 4; u++) {
                    int i = glo + lane + 32 * u;
                    if (i < ghi) __stcs(dG + i, g_r[u]);
                }
            }
        }
    }
}

// ---------------------------------------------------------------------------
extern "C" void kernel_launch(void* const* d_in, const int* in_sizes, int n_in,
                              void* d_out, int out_size) {
    const float* A    = (const float*)d_in[0];  // (128, 2048)
    const float* st   = (const float*)d_in[1];  // (1500,)
    const float* init = (const float*)d_in[2];  // (128, 250)
    int off = (n_in >= 8) ? 1 : 0;              // skip n_repeats scalar if present
    const float* sf = (const float*)d_in[3 + off];  // (2048,)
    const float* tf = (const float*)d_in[4 + off];  // (250,)
    const float* fb = (const float*)d_in[5 + off];  // (250,)
    const float* bi = (const float*)d_in[6 + off];  // (1,)

    k_all<<<B, 1024>>>(A, st, init, sf, tf, fb, bi, (float*)d_out);
}

// round 14
// speedup vs baseline: 1.8317x; 1.0406x over previous
#include <cuda_runtime.h>

// Problem constants (fixed by setup_inputs)
#define B     128
#define NPIX  2048
#define NBINS 1500
#define NBF   250
#define NREP  256
#define TSIM  1250   // len_bins_sim
#define NBLK  40     // ceil(TSIM/32)
#define N1    ((size_t)B * NREP * NBINS)   // start of gensig region in d_out

#define NCW    14    // copy warps per CTA (warps 0..13)
#define CSEG   8     // segments per copy chunk (5 chunks of 8)
#define NCHK   5
#define RHALF  128   // repeats handled per CTA

__device__ __forceinline__ float ftanh(float x) {
    float r; asm("tanh.approx.f32 %0, %1;" : "=f"(r) : "f"(x)); return r;
}

// ---------------------------------------------------------------------------
// ONE kernel, 256 CTAs x 512 threads: TWO CTAs per batch, each redundantly
// running the identical (deterministic) serial chain, each writing its own
// half of the 256 repeats. Rationale: the per-SM store drain rate is the
// measured invariant (~15 B/cyc/SM across R4/R10-R13); 128 CTAs used only
// 128 SMs. 256 CTAs cover all 148 SMs with zero cross-CTA synchronization
// (duplicating the 1-warp chain is free; cross-CTA flags were the R8 trap).
//
//   warp 15   : serial chain via tanh identity, 32 steps/iteration
//   warp 14   : pipelined precompute of next block's history-only partials
//   warps 0-13: copy. Init section (250 floats/row) written IMMEDIATELY
//               (no dependency); then 5 chunks of 8 segments, spans loaded
//               into registers once and broadcast to this CTA's 128 rows.
//
// Timeline coords: tl[k]=init[k] for k<250, tl[250+t]=spike_t.
// fb_t = sum_{j=0..249} tl[t+j] * f[j].
// For block at T0, lane i (t=T0+i):
//   - taps j in [0, 217-i]   : spikes through block m-2 -> warp-14 precompute
//   - taps j in [218-i,249-i]: block m-1 spikes         -> 32-tap fixup
//   - taps j in [250-i,249]  : in-block spikes          -> serial shfl chain
// ---------------------------------------------------------------------------
__global__ __launch_bounds__(512, 2) void k_all(
    const float* __restrict__ A,    // (128, 2048)
    const float* __restrict__ st,   // (1500,)
    const float* __restrict__ init, // (128, 250)
    const float* __restrict__ sf,   // (2048,)
    const float* __restrict__ tf,   // (250,)
    const float* __restrict__ fbf,  // (250,)
    const float* __restrict__ bias, // (1,)
    float* __restrict__ out)
{
    __shared__ __align__(16) float sh_tl[1504];   // timeline (init + spikes)
    __shared__ __align__(16) float sh_f[288];     // feedback filter, zero-padded
    __shared__ __align__(16) float sh_fq[288];    // 0.25 * filter (chain taps)
    __shared__ __align__(16) float sh_g[1280];    // drive; overwritten w/ gensig
    __shared__ __align__(16) float sh_tc[256];    // timecourse filter
    __shared__ __align__(16) float sh_st[1504];   // stim_time
    __shared__ float red[512];
    __shared__ float sh_pre[2][32];
    __shared__ int   sh_prog;                     // segments produced (0..NBLK)

    int b    = blockIdx.x >> 1;
    int half = blockIdx.x & 1;                    // which 128 repeats we write
    int tid = threadIdx.x;
    int warp = tid >> 5, lane = tid & 31;
    float* outG = out + N1;

    // ------------------------- setup -------------------------
    if (tid == 0) sh_prog = 0;
    if (tid < NBF) {
        sh_f[tid]  = fbf[tid];
        sh_tc[tid] = tf[tid];
        sh_tl[tid] = init[b * NBF + tid];
    } else if (tid < 288) sh_f[tid] = 0.f;
    for (int j = tid; j < NBINS; j += 512) sh_st[j] = st[j];
    {   // spatial dot partials: 512 threads x 1 float4 = 2048 floats exactly
        const float4* row4 = (const float4*)(A + (size_t)b * NPIX);
        const float4* sf4  = (const float4*)sf;
        float4 a = row4[tid], f = sf4[tid];
        red[tid] = a.x*f.x + a.y*f.y + a.z*f.z + a.w*f.w;
    }
    __syncthreads();

    if (tid < 288) sh_fq[tid] = 0.25f * sh_f[tid];
    if (warp == 0) {   // reduce spatial dot
        float r = 0.f;
        #pragma unroll
        for (int k = 0; k < 16; k++) r += red[lane + 32 * k];
        #pragma unroll
        for (int o = 16; o > 0; o >>= 1) r += __shfl_xor_sync(0xffffffffu, r, o);
        if (lane == 0) red[0] = r;
    }
    // correlation: 3 t-values per thread (t = tid, tid+512, tid+1024)
    float corr[3];
    #pragma unroll
    for (int u = 0; u < 3; u++) {
        int t = tid + 512 * u;
        float a0 = 0, a1 = 0, a2 = 0, a3 = 0;
        if (t < TSIM) {
            for (int j = 0; j < 248; j += 4) {
                a0 = fmaf(sh_st[t + j],     sh_tc[j],     a0);
                a1 = fmaf(sh_st[t + j + 1], sh_tc[j + 1], a1);
                a2 = fmaf(sh_st[t + j + 2], sh_tc[j + 2], a2);
                a3 = fmaf(sh_st[t + j + 3], sh_tc[j + 3], a3);
            }
            a0 = fmaf(sh_st[t + 248], sh_tc[248], a0);
            a1 = fmaf(sh_st[t + 249], sh_tc[249], a1);
        }
        corr[u] = (a0 + a1) + (a2 + a3);
    }
    __syncthreads();
    {
        float fs = red[0], bv = bias[0];
        #pragma unroll
        for (int u = 0; u < 3; u++) {
            int t = tid + 512 * u;
            if (t < 1280) sh_g[t] = (t < TSIM) ? fmaf(fs, corr[u], bv) : 0.f;
        }
    }
    __syncthreads();

    // ------------------------- role split -------------------------
    if (warp == 15) {
        // ---------------- serial chain (tanh form) ----------------
        {   // block-0 precompute: all taps from initial history
            int lim = 250 - lane;
            float a0 = 0, a1 = 0, a2 = 0, a3 = 0;
            int j = 0;
            for (; j + 4 <= lim; j += 4) {
                a0 = fmaf(sh_tl[lane + j],     sh_f[j],     a0);
                a1 = fmaf(sh_tl[lane + j + 1], sh_f[j + 1], a1);
                a2 = fmaf(sh_tl[lane + j + 2], sh_f[j + 2], a2);
                a3 = fmaf(sh_tl[lane + j + 3], sh_f[j + 3], a3);
            }
            for (; j < lim; j++) a0 = fmaf(sh_tl[lane + j], sh_f[j], a0);
            sh_pre[0][lane] = (a0 + a1) + (a2 + a3);
        }
        int fchain = 250 - lane;   // chain tap base (sh_fq)
        int ffix   = 218 - lane;   // fixup tap base (sh_f)

        // per-lane constant: C = 0.25 * sum_k F_ik  (zeros pad k >= lane)
        float Ci = 0.f;
        #pragma unroll
        for (int k = 0; k < 32; k++) Ci += sh_fq[fchain + k];

        for (int m = 0; m < NBLK; m++) {
            asm volatile("bar.sync 1, 64;" ::: "memory");  // warps 14+15 only
            int T0 = m * 32, t = T0 + lane;
            float part = sh_pre[m & 1][lane] + sh_g[t];

            if (m > 0) {   // fixup: previous block's 32 spikes
                int base = 250 + T0 - 32;
                float a0 = 0, a1 = 0, a2 = 0, a3 = 0;
                #pragma unroll
                for (int k = 0; k < 32; k += 4) {
                    a0 = fmaf(sh_tl[base + k],     sh_f[ffix + k],     a0);
                    a1 = fmaf(sh_tl[base + k + 1], sh_f[ffix + k + 1], a1);
                    a2 = fmaf(sh_tl[base + k + 2], sh_f[ffix + k + 2], a2);
                    a3 = fmaf(sh_tl[base + k + 3], sh_f[ffix + k + 3], a3);
                }
                part += (a0 + a1) + (a2 + a3);
            }

            // Y = gensig/2 with folded halves: Y = 0.5*part + C.
            // Chain: Y += t_k * (0.25*F_ik); taps zero for k >= lane so each
            // lane's Y freezes at its own step; tl = tanh(final Y).
            float Y = fmaf(0.5f, part, Ci);
            float tl = 0.f;
            #pragma unroll
            for (int k = 0; k < 32; k++) {
                tl = ftanh(Y);
                float s = __shfl_sync(0xffffffffu, tl, k);
                Y = fmaf(s, sh_fq[fchain + k], Y);
            }

            int kmax = TSIM - T0; if (kmax > 32) kmax = 32;
            if (lane < kmax) {
                sh_tl[250 + t] = fmaf(0.5f, tl, 0.5f);   // spike = sigmoid(g)
                sh_g[t] = 2.0f * Y;                      // gensig
            }
            __syncwarp();
            if (lane == 0) { __threadfence_block(); *(volatile int*)&sh_prog = m + 1; }
        }
    } else if (warp == 14) {
        // ---------------- pipelined precompute ----------------
        for (int m = 0; m < NBLK; m++) {
            asm volatile("bar.sync 1, 64;" ::: "memory");
            if (m + 1 < NBLK) {   // block m+1 partials over spikes through m-1
                int T0n = m * 32 + 32;
                int lim = 218 - lane;
                float a0 = 0, a1 = 0, a2 = 0, a3 = 0;
                int j = 0;
                for (; j + 4 <= lim; j += 4) {
                    a0 = fmaf(sh_tl[T0n + lane + j],     sh_f[j],     a0);
                    a1 = fmaf(sh_tl[T0n + lane + j + 1], sh_f[j + 1], a1);
                    a2 = fmaf(sh_tl[T0n + lane + j + 2], sh_f[j + 2], a2);
                    a3 = fmaf(sh_tl[T0n + lane + j + 3], sh_f[j + 3], a3);
                }
                for (; j < lim; j++) a0 = fmaf(sh_tl[T0n + lane + j], sh_f[j], a0);
                sh_pre[(m + 1) & 1][lane] = (a0 + a1) + (a2 + a3);
            }
        }
    } else {
        // --- copy warps 0..13: this CTA's 128 repeats (register-resident) ---
        volatile int* prog = &sh_prog;
        const float2* stl2 = (const float2*)sh_tl;
        const float2* sg2  = (const float2*)sh_g;
        int rbase = b * NREP + half * RHALF;

        // init section FIRST — no dependency on the chain, starts the DRAM
        // drain immediately (32.8 MB chip-wide head start).
        {
            float2 iv[4];
            #pragma unroll
            for (int u = 0; u < 4; u++) {
                int i = lane + 32 * u;
                if (i < 125) iv[u] = stl2[i];
            }
            for (int r = warp; r < RHALF; r += NCW) {
                float2* dT = (float2*)(out + (size_t)(rbase + r) * NBINS);
                #pragma unroll
                for (int u = 0; u < 4; u++) {
                    int i = lane + 32 * u;
                    if (i < 125) __stcs(dT + i, iv[u]);
                }
            }
        }

        for (int c = 0; c < NCHK; c++) {
            while (*prog < CSEG * (c + 1)) __nanosleep(64);
            // producer's __threadfence_block before the flag store orders the
            // spike/gensig STS ahead of the flag; no consumer fence needed.

            int tlo = 125 + 128 * c;                   // timeline float2 range
            int thi = tlo + 128; if (thi > 750) thi = 750;
            int glo = 128 * c;                         // gensig float2 range
            int ghi = glo + 128; if (ghi > 625) ghi = 625;

            // load spans into registers ONCE per chunk
            float2 tl_r[4], g_r[4];
            #pragma unroll
            for (int u = 0; u < 4; u++) {
                int i = tlo + lane + 32 * u;
                if (i < thi) tl_r[u] = stl2[i];
            }
            #pragma unroll
            for (int u = 0; u < 4; u++) {
                int i = glo + lane + 32 * u;
                if (i < ghi) g_r[u] = sg2[i];
            }

            // per-row loop: pure stores
            for (int r = warp; r < RHALF; r += NCW) {
                size_t row = (size_t)(rbase + r);
                float2* dT = (float2*)(out + row * NBINS);
                float2* dG = (float2*)(outG + row * TSIM);
                #pragma unroll
                for (int u = 0; u < 4; u++) {
                    int i = tlo + lane + 32 * u;
                    if (i < thi) __stcs(dT + i, tl_r[u]);
                }
                #pragma unroll
                for (int u = 0; u < 4; u++) {
                    int i = glo + lane + 32 * u;
                    if (i < ghi) __stcs(dG + i, g_r[u]);
                }
            }
        }
    }
}

// ---------------------------------------------------------------------------
extern "C" void kernel_launch(void* const* d_in, const int* in_sizes, int n_in,
                              void* d_out, int out_size) {
    const float* A    = (const float*)d_in[0];  // (128, 2048)
    const float* st   = (const float*)d_in[1];  // (1500,)
    const float* init = (const float*)d_in[2];  // (128, 250)
    int off = (n_in >= 8) ? 1 : 0;              // skip n_repeats scalar if present
    const float* sf = (const float*)d_in[3 + off];  // (2048,)
    const float* tf = (const float*)d_in[4 + off];  // (250,)
    const float* fb = (const float*)d_in[5 + off];  // (250,)
    const float* bi = (const float*)d_in[6 + off];  // (1,)

    k_all<<<2 * B, 512>>>(A, st, init, sf, tf, fb, bi, (float*)d_out);
}